// round 6
// baseline (speedup 1.0000x reference)
#include <cuda_runtime.h>

// dis_loss: mean over (B*21) per-joint Euclidean distances of [B,21,3] fp32 diffs.
// B = 262144, 63 floats/row. Pure HBM-bound streaming reduction (132 MB read).

#define B_ROWS      262144
#define N_JOINTS    21
#define TOTAL_F     (B_ROWS * N_JOINTS * 3)        // 16,515,072 floats per tensor
#define FLOATS_PER_THREAD 12                       // 4 joints = 3 float4 loads
#define UNITS       (TOTAL_F / FLOATS_PER_THREAD)  // 1,376,256 (exact)
#define THREADS     256
#define BLOCKS      (UNITS / THREADS)              // 5376 (exact)

__device__ float    g_acc;    // zero-initialized at module load; reset by last block
__device__ unsigned g_count;

__device__ __forceinline__ float joint_dist(float dx, float dy, float dz) {
    return sqrtf(fmaf(dx, dx, fmaf(dy, dy, dz * dz)));
}

__global__ void __launch_bounds__(THREADS)
dis_loss_kernel(const float4* __restrict__ pred,
                const float4* __restrict__ tgt,
                float* __restrict__ out) {
    const int idx  = blockIdx.x * THREADS + threadIdx.x;
    const int base = idx * 3;

    // Front-batched independent loads: MLP = 6 LDG.128
    float4 p0 = pred[base + 0];
    float4 p1 = pred[base + 1];
    float4 p2 = pred[base + 2];
    float4 t0 = tgt[base + 0];
    float4 t1 = tgt[base + 1];
    float4 t2 = tgt[base + 2];

    // 12 consecutive floats = joints [0..3] (layout is ...,x,y,z,x,y,z,...)
    float s;
    s  = joint_dist(p0.x - t0.x, p0.y - t0.y, p0.z - t0.z);
    s += joint_dist(p0.w - t0.w, p1.x - t1.x, p1.y - t1.y);
    s += joint_dist(p1.z - t1.z, p1.w - t1.w, p2.x - t2.x);
    s += joint_dist(p2.y - t2.y, p2.z - t2.z, p2.w - t2.w);

    // Warp reduction
    #pragma unroll
    for (int off = 16; off > 0; off >>= 1)
        s += __shfl_xor_sync(0xFFFFFFFFu, s, off);

    // Block reduction
    __shared__ float warp_sums[THREADS / 32];
    const int lane = threadIdx.x & 31;
    const int warp = threadIdx.x >> 5;
    if (lane == 0) warp_sums[warp] = s;
    __syncthreads();

    __shared__ bool is_last;
    if (threadIdx.x == 0) {
        float bsum = 0.0f;
        #pragma unroll
        for (int w = 0; w < THREADS / 32; w++) bsum += warp_sums[w];
        atomicAdd(&g_acc, bsum);
        __threadfence();
        unsigned prev = atomicAdd(&g_count, 1u);
        is_last = (prev == (unsigned)(gridDim.x - 1));
    }
    __syncthreads();

    // Last block finalizes and resets state for the next graph replay.
    if (is_last && threadIdx.x == 0) {
        float total = atomicAdd(&g_acc, 0.0f);  // serialized-visible read
        out[0] = total * (1.0f / (float)((long long)B_ROWS * N_JOINTS));
        g_acc   = 0.0f;
        g_count = 0u;
    }
}

extern "C" void kernel_launch(void* const* d_in, const int* in_sizes, int n_in,
                              void* d_out, int out_size) {
    const float4* pred = (const float4*)d_in[0];
    const float4* tgt  = (const float4*)d_in[1];
    float* out = (float*)d_out;
    dis_loss_kernel<<<BLOCKS, THREADS>>>(pred, tgt, out);
}